// round 12
// baseline (speedup 1.0000x reference)
#include <cuda_runtime.h>
#include <math.h>

#define DIM   4096
#define CAP   8192
#define TOPK  8
#define NV4   (DIM / 4)          // 1024 float4 per row

// Scratch (no allocations allowed in kernel_launch).
__device__ float g_weighted[CAP];
__device__ int   g_topidx[TOPK];
__device__ float g_retrieved[DIM];

// ---------------------------------------------------------------------------
// Kernel 1: fused score pass, 4 ROWS PER BLOCK @ 512 threads.
// mb loads use __ldcv (no L1/L2 allocation): per B300 model LDG.cv streams at
// the same LTS cap as ldcs, but never evicts W_dec from L2 -> gemv stays
// L2-fed. 8 independent LDG.128 per thread; one reduction tail per 64 KB.
// Stride-7 block permutation (measured +7% DRAM bw on this pattern).
// ---------------------------------------------------------------------------
__global__ __launch_bounds__(512) void score_kernel(
    const float* __restrict__ q,
    const float* __restrict__ mb,
    const float* __restrict__ imp,
    const float* __restrict__ age)
{
    const int p   = (int)((blockIdx.x * 7u) & 2047u);   // bijection on [0,2048)
    const int r0  = p * 4;
    const int tid = threadIdx.x;
    const float4* base = reinterpret_cast<const float4*>(mb) + (size_t)r0 * NV4;
    const float4* qv   = reinterpret_cast<const float4*>(q);

    float d0 = 0.f, d1 = 0.f, d2 = 0.f, d3 = 0.f;
    float n0 = 0.f, n1 = 0.f, n2 = 0.f, n3 = 0.f;
    float qn = 0.f;

    #pragma unroll
    for (int u = 0; u < 2; u++) {
        int i = tid + u * 512;
        float4 b  = qv[i];
        float4 a0 = __ldcv(&base[i]);
        float4 a1 = __ldcv(&base[NV4 + i]);
        float4 a2 = __ldcv(&base[2 * NV4 + i]);
        float4 a3 = __ldcv(&base[3 * NV4 + i]);
        qn += b.x * b.x + b.y * b.y + b.z * b.z + b.w * b.w;
        d0 += a0.x * b.x + a0.y * b.y + a0.z * b.z + a0.w * b.w;
        n0 += a0.x * a0.x + a0.y * a0.y + a0.z * a0.z + a0.w * a0.w;
        d1 += a1.x * b.x + a1.y * b.y + a1.z * b.z + a1.w * b.w;
        n1 += a1.x * a1.x + a1.y * a1.y + a1.z * a1.z + a1.w * a1.w;
        d2 += a2.x * b.x + a2.y * b.y + a2.z * b.z + a2.w * b.w;
        n2 += a2.x * a2.x + a2.y * a2.y + a2.z * a2.z + a2.w * a2.w;
        d3 += a3.x * b.x + a3.y * b.y + a3.z * b.z + a3.w * b.w;
        n3 += a3.x * a3.x + a3.y * a3.y + a3.z * a3.z + a3.w * a3.w;
    }

    #pragma unroll
    for (int o = 16; o > 0; o >>= 1) {
        d0 += __shfl_down_sync(0xffffffffu, d0, o);
        n0 += __shfl_down_sync(0xffffffffu, n0, o);
        d1 += __shfl_down_sync(0xffffffffu, d1, o);
        n1 += __shfl_down_sync(0xffffffffu, n1, o);
        d2 += __shfl_down_sync(0xffffffffu, d2, o);
        n2 += __shfl_down_sync(0xffffffffu, n2, o);
        d3 += __shfl_down_sync(0xffffffffu, d3, o);
        n3 += __shfl_down_sync(0xffffffffu, n3, o);
        qn += __shfl_down_sync(0xffffffffu, qn, o);
    }

    __shared__ float sd[4][16], sn[4][16], sq[16];
    const int w = tid >> 5;
    if ((tid & 31) == 0) {
        sd[0][w] = d0; sn[0][w] = n0;
        sd[1][w] = d1; sn[1][w] = n1;
        sd[2][w] = d2; sn[2][w] = n2;
        sd[3][w] = d3; sn[3][w] = n3;
        sq[w] = qn;
    }
    __syncthreads();

    // 4 warps finalize 4 rows in parallel (lane 0 of warps 0..3)
    if (w < 4 && (tid & 31) == 0) {
        float D = 0.f, N = 0.f, Q = 0.f;
        #pragma unroll
        for (int i = 0; i < 16; i++) { D += sd[w][i]; N += sn[w][i]; Q += sq[i]; }
        int r = r0 + w;
        float sim = D / fmaxf(sqrtf(Q) * sqrtf(N), 1e-8f);
        g_weighted[r] = sim * imp[r] * expf(-0.001f * age[r]);
    }
}

// ---------------------------------------------------------------------------
// Kernel 2: top-8 of 8192 + gather/mean, fused. Single block of 1024 threads.
// ---------------------------------------------------------------------------
__global__ __launch_bounds__(1024) void topk_gather_kernel(const float* __restrict__ mb)
{
    __shared__ float w[CAP];          // 32 KB
    __shared__ float bv[32];
    __shared__ int   bi[32];
    __shared__ int   s_idx[TOPK];

    const int tid = threadIdx.x;
    for (int i = tid; i < CAP; i += 1024) w[i] = g_weighted[i];
    __syncthreads();

    for (int k = 0; k < TOPK; k++) {
        float best = -3.0e38f;
        int   idx  = -1;
        #pragma unroll
        for (int i = tid; i < CAP; i += 1024) {
            float v = w[i];
            if (v > best) { best = v; idx = i; }   // strict > keeps min index on ties
        }
        #pragma unroll
        for (int o = 16; o > 0; o >>= 1) {
            float ov = __shfl_down_sync(0xffffffffu, best, o);
            int   oi = __shfl_down_sync(0xffffffffu, idx, o);
            if (ov > best || (ov == best && oi < idx)) { best = ov; idx = oi; }
        }
        if ((tid & 31) == 0) { bv[tid >> 5] = best; bi[tid >> 5] = idx; }
        __syncthreads();
        if (tid == 0) {
            float bb = bv[0]; int ii = bi[0];
            #pragma unroll
            for (int j = 1; j < 32; j++)
                if (bv[j] > bb || (bv[j] == bb && bi[j] < ii)) { bb = bv[j]; ii = bi[j]; }
            s_idx[k] = ii;
            g_topidx[k] = ii;
            w[ii] = -3.0e38f;           // exclude from next pass
        }
        __syncthreads();
    }

    // gather: retrieved = mean of the 8 selected rows (1 float4 per thread)
    const float4* mbv = reinterpret_cast<const float4*>(mb);
    const int j = tid;                  // 0..1023 float4 lanes
    float4 acc = make_float4(0.f, 0.f, 0.f, 0.f);
    #pragma unroll
    for (int t = 0; t < TOPK; t++) {
        float4 x = __ldg(&mbv[(size_t)s_idx[t] * NV4 + j]);
        acc.x += x.x; acc.y += x.y; acc.z += x.z; acc.w += x.w;
    }
    reinterpret_cast<float4*>(g_retrieved)[j] =
        make_float4(acc.x * 0.125f, acc.y * 0.125f, acc.z * 0.125f, acc.w * 0.125f);
}

// ---------------------------------------------------------------------------
// Kernel 3: decode GEMV, 2 rows/block. W_dec default-cached -> fully
// L2-resident across graph replays now that the mb stream is .cv (no L2
// allocation at all).
// ---------------------------------------------------------------------------
__global__ __launch_bounds__(256) void gemv_kernel(
    const float* __restrict__ W,
    const float* __restrict__ b,
    float* __restrict__ out)
{
    const int r0  = blockIdx.x * 2;
    const int r1  = r0 + 1;
    const int tid = threadIdx.x;
    const float4* w0 = reinterpret_cast<const float4*>(W) + (size_t)r0 * NV4;
    const float4* w1 = reinterpret_cast<const float4*>(W) + (size_t)r1 * NV4;
    const float4* rv = reinterpret_cast<const float4*>(g_retrieved);

    float a0 = 0.f, a1 = 0.f;
    #pragma unroll
    for (int u = 0; u < 4; u++) {
        int i = tid + u * 256;
        float4 x0 = __ldg(&w0[i]);
        float4 x1 = __ldg(&w1[i]);
        float4 v  = rv[i];
        a0 += x0.x * v.x + x0.y * v.y + x0.z * v.z + x0.w * v.w;
        a1 += x1.x * v.x + x1.y * v.y + x1.z * v.z + x1.w * v.w;
    }
    #pragma unroll
    for (int o = 16; o > 0; o >>= 1) {
        a0 += __shfl_down_sync(0xffffffffu, a0, o);
        a1 += __shfl_down_sync(0xffffffffu, a1, o);
    }

    __shared__ float sa[8], sb[8];
    const int w = tid >> 5;
    if ((tid & 31) == 0) { sa[w] = a0; sb[w] = a1; }
    __syncthreads();
    if (tid == 0) {
        float t0 = 0.f, t1 = 0.f;
        #pragma unroll
        for (int i = 0; i < 8; i++) { t0 += sa[i]; t1 += sb[i]; }
        out[r0] = t0 + b[r0];
        out[r1] = t1 + b[r1];
    }
}

// ---------------------------------------------------------------------------
extern "C" void kernel_launch(void* const* d_in, const int* in_sizes, int n_in,
                              void* d_out, int out_size)
{
    const float* q   = (const float*)d_in[0];  // [4096]
    const float* mb  = (const float*)d_in[1];  // [8192, 4096]
    const float* imp = (const float*)d_in[2];  // [8192]
    const float* age = (const float*)d_in[3];  // [8192]
    const float* W   = (const float*)d_in[4];  // [4096, 4096]
    const float* b   = (const float*)d_in[5];  // [4096]
    float* out = (float*)d_out;                // [4096]

    score_kernel<<<CAP / 4, 512>>>(q, mb, imp, age);
    topk_gather_kernel<<<1, 1024>>>(mb);
    gemv_kernel<<<DIM / 2, 256>>>(W, b, out);
}

// round 13
// speedup vs baseline: 1.0659x; 1.0659x over previous
#include <cuda_runtime.h>
#include <math.h>

#define DIM   4096
#define CAP   8192
#define TOPK  8
#define NV4   (DIM / 4)          // 1024 float4 per row

// Scratch (no allocations allowed in kernel_launch).
__device__ float g_weighted[CAP];
__device__ int   g_topidx[TOPK];
__device__ float g_retrieved[DIM];

// ---------------------------------------------------------------------------
// Kernel 1: fused score pass — EXACT R9 shape (2 rows/block @ 256, stride-7
// permutation), with the single change: mb loads via __ldcv (no L1/L2
// allocation at all), so the 128 MiB sweep cannot erode W_dec's L2 residency
// between graph replays.
// ---------------------------------------------------------------------------
__global__ __launch_bounds__(256) void score_kernel(
    const float* __restrict__ q,
    const float* __restrict__ mb,
    const float* __restrict__ imp,
    const float* __restrict__ age)
{
    const int p   = (int)((blockIdx.x * 7u) & 4095u);   // bijection on [0,4096)
    const int r0  = p * 2;
    const int r1  = r0 + 1;
    const int tid = threadIdx.x;
    const float4* m0 = reinterpret_cast<const float4*>(mb) + (size_t)r0 * NV4;
    const float4* m1 = reinterpret_cast<const float4*>(mb) + (size_t)r1 * NV4;
    const float4* qv = reinterpret_cast<const float4*>(q);

    float d0 = 0.f, n0 = 0.f, d1 = 0.f, n1 = 0.f, qn = 0.f;
    #pragma unroll
    for (int u = 0; u < 4; u++) {
        int i = tid + u * 256;
        float4 a0 = __ldcv(&m0[i]);    // no-allocate stream
        float4 a1 = __ldcv(&m1[i]);
        float4 b  = qv[i];
        d0 += a0.x * b.x + a0.y * b.y + a0.z * b.z + a0.w * b.w;
        n0 += a0.x * a0.x + a0.y * a0.y + a0.z * a0.z + a0.w * a0.w;
        d1 += a1.x * b.x + a1.y * b.y + a1.z * b.z + a1.w * b.w;
        n1 += a1.x * a1.x + a1.y * a1.y + a1.z * a1.z + a1.w * a1.w;
        qn += b.x * b.x + b.y * b.y + b.z * b.z + b.w * b.w;
    }

    #pragma unroll
    for (int o = 16; o > 0; o >>= 1) {
        d0 += __shfl_down_sync(0xffffffffu, d0, o);
        n0 += __shfl_down_sync(0xffffffffu, n0, o);
        d1 += __shfl_down_sync(0xffffffffu, d1, o);
        n1 += __shfl_down_sync(0xffffffffu, n1, o);
        qn += __shfl_down_sync(0xffffffffu, qn, o);
    }

    __shared__ float s0[8], s1[8], s2[8], s3[8], s4[8];
    const int w = tid >> 5;
    if ((tid & 31) == 0) { s0[w] = d0; s1[w] = n0; s2[w] = d1; s3[w] = n1; s4[w] = qn; }
    __syncthreads();

    if (tid == 0) {
        float D0 = 0.f, N0 = 0.f, D1 = 0.f, N1 = 0.f, Q = 0.f;
        #pragma unroll
        for (int i = 0; i < 8; i++) {
            D0 += s0[i]; N0 += s1[i]; D1 += s2[i]; N1 += s3[i]; Q += s4[i];
        }
        float qs = sqrtf(Q);
        float sim0 = D0 / fmaxf(qs * sqrtf(N0), 1e-8f);
        float sim1 = D1 / fmaxf(qs * sqrtf(N1), 1e-8f);
        g_weighted[r0] = sim0 * imp[r0] * expf(-0.001f * age[r0]);
        g_weighted[r1] = sim1 * imp[r1] * expf(-0.001f * age[r1]);
    }
}

// ---------------------------------------------------------------------------
// Kernel 2: top-8 of 8192 + gather/mean, fused. Single block of 1024 threads.
// ---------------------------------------------------------------------------
__global__ __launch_bounds__(1024) void topk_gather_kernel(const float* __restrict__ mb)
{
    __shared__ float w[CAP];          // 32 KB
    __shared__ float bv[32];
    __shared__ int   bi[32];
    __shared__ int   s_idx[TOPK];

    const int tid = threadIdx.x;
    for (int i = tid; i < CAP; i += 1024) w[i] = g_weighted[i];
    __syncthreads();

    for (int k = 0; k < TOPK; k++) {
        float best = -3.0e38f;
        int   idx  = -1;
        #pragma unroll
        for (int i = tid; i < CAP; i += 1024) {
            float v = w[i];
            if (v > best) { best = v; idx = i; }   // strict > keeps min index on ties
        }
        #pragma unroll
        for (int o = 16; o > 0; o >>= 1) {
            float ov = __shfl_down_sync(0xffffffffu, best, o);
            int   oi = __shfl_down_sync(0xffffffffu, idx, o);
            if (ov > best || (ov == best && oi < idx)) { best = ov; idx = oi; }
        }
        if ((tid & 31) == 0) { bv[tid >> 5] = best; bi[tid >> 5] = idx; }
        __syncthreads();
        if (tid == 0) {
            float bb = bv[0]; int ii = bi[0];
            #pragma unroll
            for (int j = 1; j < 32; j++)
                if (bv[j] > bb || (bv[j] == bb && bi[j] < ii)) { bb = bv[j]; ii = bi[j]; }
            s_idx[k] = ii;
            g_topidx[k] = ii;
            w[ii] = -3.0e38f;           // exclude from next pass
        }
        __syncthreads();
    }

    // gather: retrieved = mean of the 8 selected rows (1 float4 per thread)
    const float4* mbv = reinterpret_cast<const float4*>(mb);
    const int j = tid;                  // 0..1023 float4 lanes
    float4 acc = make_float4(0.f, 0.f, 0.f, 0.f);
    #pragma unroll
    for (int t = 0; t < TOPK; t++) {
        float4 x = __ldg(&mbv[(size_t)s_idx[t] * NV4 + j]);
        acc.x += x.x; acc.y += x.y; acc.z += x.z; acc.w += x.w;
    }
    reinterpret_cast<float4*>(g_retrieved)[j] =
        make_float4(acc.x * 0.125f, acc.y * 0.125f, acc.z * 0.125f, acc.w * 0.125f);
}

// ---------------------------------------------------------------------------
// Kernel 3: decode GEMV, 2 rows/block. W_dec default-cached; with the mb
// stream now non-allocating, W should be fully L2-resident across replays.
// ---------------------------------------------------------------------------
__global__ __launch_bounds__(256) void gemv_kernel(
    const float* __restrict__ W,
    const float* __restrict__ b,
    float* __restrict__ out)
{
    const int r0  = blockIdx.x * 2;
    const int r1  = r0 + 1;
    const int tid = threadIdx.x;
    const float4* w0 = reinterpret_cast<const float4*>(W) + (size_t)r0 * NV4;
    const float4* w1 = reinterpret_cast<const float4*>(W) + (size_t)r1 * NV4;
    const float4* rv = reinterpret_cast<const float4*>(g_retrieved);

    float a0 = 0.f, a1 = 0.f;
    #pragma unroll
    for (int u = 0; u < 4; u++) {
        int i = tid + u * 256;
        float4 x0 = __ldg(&w0[i]);
        float4 x1 = __ldg(&w1[i]);
        float4 v  = rv[i];
        a0 += x0.x * v.x + x0.y * v.y + x0.z * v.z + x0.w * v.w;
        a1 += x1.x * v.x + x1.y * v.y + x1.z * v.z + x1.w * v.w;
    }
    #pragma unroll
    for (int o = 16; o > 0; o >>= 1) {
        a0 += __shfl_down_sync(0xffffffffu, a0, o);
        a1 += __shfl_down_sync(0xffffffffu, a1, o);
    }

    __shared__ float sa[8], sb[8];
    const int w = tid >> 5;
    if ((tid & 31) == 0) { sa[w] = a0; sb[w] = a1; }
    __syncthreads();
    if (tid == 0) {
        float t0 = 0.f, t1 = 0.f;
        #pragma unroll
        for (int i = 0; i < 8; i++) { t0 += sa[i]; t1 += sb[i]; }
        out[r0] = t0 + b[r0];
        out[r1] = t1 + b[r1];
    }
}

// ---------------------------------------------------------------------------
extern "C" void kernel_launch(void* const* d_in, const int* in_sizes, int n_in,
                              void* d_out, int out_size)
{
    const float* q   = (const float*)d_in[0];  // [4096]
    const float* mb  = (const float*)d_in[1];  // [8192, 4096]
    const float* imp = (const float*)d_in[2];  // [8192]
    const float* age = (const float*)d_in[3];  // [8192]
    const float* W   = (const float*)d_in[4];  // [4096, 4096]
    const float* b   = (const float*)d_in[5];  // [4096]
    float* out = (float*)d_out;                // [4096]

    score_kernel<<<CAP / 2, 256>>>(q, mb, imp, age);
    topk_gather_kernel<<<1, 1024>>>(mb);
    gemv_kernel<<<DIM / 2, 256>>>(W, b, out);
}

// round 14
// speedup vs baseline: 1.1110x; 1.0424x over previous
#include <cuda_runtime.h>
#include <math.h>

#define DIM   4096
#define CAP   8192
#define TOPK  8
#define NV4   (DIM / 4)          // 1024 float4 per row

// Scratch (no allocations allowed in kernel_launch).
__device__ float g_weighted[CAP];
__device__ float g_retrieved[DIM];
__device__ int   g_flag = 0;     // set by fused-gemv block 0 after retrieved ready

// ---------------------------------------------------------------------------
// Kernel 1: fused score pass — EXACT R9 config (best measured: 2 rows/block,
// 256 threads, stride-7 permutation, __ldcs streaming). Also resets g_flag
// for this replay (safe: previous replay's gemv kernel has fully completed).
// ---------------------------------------------------------------------------
__global__ __launch_bounds__(256) void score_kernel(
    const float* __restrict__ q,
    const float* __restrict__ mb,
    const float* __restrict__ imp,
    const float* __restrict__ age)
{
    if (blockIdx.x == 0 && threadIdx.x == 0) g_flag = 0;

    const int p   = (int)((blockIdx.x * 7u) & 4095u);   // bijection on [0,4096)
    const int r0  = p * 2;
    const int r1  = r0 + 1;
    const int tid = threadIdx.x;
    const float4* m0 = reinterpret_cast<const float4*>(mb) + (size_t)r0 * NV4;
    const float4* m1 = reinterpret_cast<const float4*>(mb) + (size_t)r1 * NV4;
    const float4* qv = reinterpret_cast<const float4*>(q);

    float d0 = 0.f, n0 = 0.f, d1 = 0.f, n1 = 0.f, qn = 0.f;
    #pragma unroll
    for (int u = 0; u < 4; u++) {
        int i = tid + u * 256;
        float4 a0 = __ldcs(&m0[i]);
        float4 a1 = __ldcs(&m1[i]);
        float4 b  = qv[i];
        d0 += a0.x * b.x + a0.y * b.y + a0.z * b.z + a0.w * b.w;
        n0 += a0.x * a0.x + a0.y * a0.y + a0.z * a0.z + a0.w * a0.w;
        d1 += a1.x * b.x + a1.y * b.y + a1.z * b.z + a1.w * b.w;
        n1 += a1.x * a1.x + a1.y * a1.y + a1.z * a1.z + a1.w * a1.w;
        qn += b.x * b.x + b.y * b.y + b.z * b.z + b.w * b.w;
    }

    #pragma unroll
    for (int o = 16; o > 0; o >>= 1) {
        d0 += __shfl_down_sync(0xffffffffu, d0, o);
        n0 += __shfl_down_sync(0xffffffffu, n0, o);
        d1 += __shfl_down_sync(0xffffffffu, d1, o);
        n1 += __shfl_down_sync(0xffffffffu, n1, o);
        qn += __shfl_down_sync(0xffffffffu, qn, o);
    }

    __shared__ float s0[8], s1[8], s2[8], s3[8], s4[8];
    const int w = tid >> 5;
    if ((tid & 31) == 0) { s0[w] = d0; s1[w] = n0; s2[w] = d1; s3[w] = n1; s4[w] = qn; }
    __syncthreads();

    if (tid == 0) {
        float D0 = 0.f, N0 = 0.f, D1 = 0.f, N1 = 0.f, Q = 0.f;
        #pragma unroll
        for (int i = 0; i < 8; i++) {
            D0 += s0[i]; N0 += s1[i]; D1 += s2[i]; N1 += s3[i]; Q += s4[i];
        }
        float qs = sqrtf(Q);
        float sim0 = D0 / fmaxf(qs * sqrtf(N0), 1e-8f);
        float sim1 = D1 / fmaxf(qs * sqrtf(N1), 1e-8f);
        g_weighted[r0] = sim0 * imp[r0] * expf(-0.001f * age[r0]);
        g_weighted[r1] = sim1 * imp[r1] * expf(-0.001f * age[r1]);
    }
}

// ---------------------------------------------------------------------------
// Kernel 2: FUSED topk + gather + gemv. Grid 2048 x 256 threads, 2 rows/block.
// Block 0: top-8 (register argmax, min-index ties) + retrieved, fence, flag.
// All blocks: prefetch W rows into registers FIRST (overlaps block-0's serial
// topk with W streaming), leader-spin on flag, then FMA + reduce + store.
// Deterministic: result depends only on inputs; flag reset by kernel 1.
// ---------------------------------------------------------------------------
__global__ __launch_bounds__(256) void gemv_fused_kernel(
    const float* __restrict__ W,
    const float* __restrict__ b,
    const float* __restrict__ mb,
    float* __restrict__ out)
{
    const int bid = blockIdx.x;
    const int tid = threadIdx.x;
    const int r0  = bid * 2;
    const int r1  = r0 + 1;
    const float4* w0p = reinterpret_cast<const float4*>(W) + (size_t)r0 * NV4;
    const float4* w1p = reinterpret_cast<const float4*>(W) + (size_t)r1 * NV4;

    if (bid == 0) {
        // ---- top-8 of 8192 in registers (32 scores per thread) ----
        float v[32];
        #pragma unroll
        for (int j = 0; j < 32; j++)
            v[j] = g_weighted[tid + 256 * j];

        __shared__ float s_wmax[8];
        __shared__ float s_gmax;
        __shared__ int   s_arg;
        __shared__ int   s_idx[TOPK];

        for (int k = 0; k < TOPK; k++) {
            float mx = v[0];
            #pragma unroll
            for (int j = 1; j < 32; j++) mx = fmaxf(mx, v[j]);
            #pragma unroll
            for (int o = 16; o > 0; o >>= 1)
                mx = fmaxf(mx, __shfl_xor_sync(0xffffffffu, mx, o));
            if ((tid & 31) == 0) s_wmax[tid >> 5] = mx;
            if (tid == 0) s_arg = 0x7fffffff;
            __syncthreads();
            if (tid == 0) {
                float g = s_wmax[0];
                #pragma unroll
                for (int j = 1; j < 8; j++) g = fmaxf(g, s_wmax[j]);
                s_gmax = g;
            }
            __syncthreads();
            float g = s_gmax;
            #pragma unroll
            for (int j = 0; j < 32; j++)
                if (v[j] == g) atomicMin(&s_arg, tid + 256 * j);  // min index on ties
            __syncthreads();
            int win = s_arg;
            if (tid == 0) s_idx[k] = win;
            if ((win & 255) == tid) v[win >> 8] = -3.0e38f;       // remove winner
            __syncthreads();
        }

        // ---- gather: retrieved = mean of 8 selected rows ----
        const float4* mbv = reinterpret_cast<const float4*>(mb);
        #pragma unroll
        for (int u = 0; u < 4; u++) {
            int j = tid + u * 256;
            float4 acc = make_float4(0.f, 0.f, 0.f, 0.f);
            #pragma unroll
            for (int t = 0; t < TOPK; t++) {
                float4 x = __ldg(&mbv[(size_t)s_idx[t] * NV4 + j]);
                acc.x += x.x; acc.y += x.y; acc.z += x.z; acc.w += x.w;
            }
            reinterpret_cast<float4*>(g_retrieved)[j] =
                make_float4(acc.x * 0.125f, acc.y * 0.125f, acc.z * 0.125f, acc.w * 0.125f);
        }
        __threadfence();          // publish retrieved (each thread's stores)
        __syncthreads();          // all threads' stores fenced before flag
        if (tid == 0) atomicExch(&g_flag, 1);
    }

    // ---- all blocks: prefetch W rows into registers (overlaps topk) ----
    float4 wr0[4], wr1[4];
    #pragma unroll
    for (int u = 0; u < 4; u++) {
        int i = tid + u * 256;
        wr0[u] = __ldg(&w0p[i]);
        wr1[u] = __ldg(&w1p[i]);
    }

    // ---- wait for retrieved (leader spins, block barrier broadcasts) ----
    if (tid == 0) {
        while (atomicAdd(&g_flag, 0) == 0) { }
    }
    __syncthreads();
    __threadfence();              // order subsequent loads after flag observation

    const float4* rv = reinterpret_cast<const float4*>(g_retrieved);
    float a0 = 0.f, a1 = 0.f;
    #pragma unroll
    for (int u = 0; u < 4; u++) {
        int i = tid + u * 256;
        float4 v4 = __ldcg(&rv[i]);   // bypass L1 (freshly written by block 0)
        a0 += wr0[u].x * v4.x + wr0[u].y * v4.y + wr0[u].z * v4.z + wr0[u].w * v4.w;
        a1 += wr1[u].x * v4.x + wr1[u].y * v4.y + wr1[u].z * v4.z + wr1[u].w * v4.w;
    }
    #pragma unroll
    for (int o = 16; o > 0; o >>= 1) {
        a0 += __shfl_down_sync(0xffffffffu, a0, o);
        a1 += __shfl_down_sync(0xffffffffu, a1, o);
    }

    __shared__ float sa[8], sb[8];
    const int w = tid >> 5;
    if ((tid & 31) == 0) { sa[w] = a0; sb[w] = a1; }
    __syncthreads();
    if (tid == 0) {
        float t0 = 0.f, t1 = 0.f;
        #pragma unroll
        for (int i = 0; i < 8; i++) { t0 += sa[i]; t1 += sb[i]; }
        out[r0] = t0 + b[r0];
        out[r1] = t1 + b[r1];
    }
}

// ---------------------------------------------------------------------------
extern "C" void kernel_launch(void* const* d_in, const int* in_sizes, int n_in,
                              void* d_out, int out_size)
{
    const float* q   = (const float*)d_in[0];  // [4096]
    const float* mb  = (const float*)d_in[1];  // [8192, 4096]
    const float* imp = (const float*)d_in[2];  // [8192]
    const float* age = (const float*)d_in[3];  // [8192]
    const float* W   = (const float*)d_in[4];  // [4096, 4096]
    const float* b   = (const float*)d_in[5];  // [4096]
    float* out = (float*)d_out;                // [4096]

    score_kernel<<<CAP / 2, 256>>>(q, mb, imp, age);
    gemv_fused_kernel<<<DIM / 2, 256>>>(W, b, mb, out);
}

// round 16
// speedup vs baseline: 1.2088x; 1.0880x over previous
#include <cuda_runtime.h>
#include <math.h>

#define DIM   4096
#define CAP   8192
#define TOPK  8
#define NV4   (DIM / 4)          // 1024 float4 per row

// Scratch (no allocations allowed in kernel_launch).
__device__ float g_weighted[CAP];
__device__ float g_retrieved[DIM];

// ---------------------------------------------------------------------------
// Kernel 1: fused score pass — EXACT R9 config (best measured: 2 rows/block,
// 256 threads, stride-7 permutation, __ldcs streaming).
// ---------------------------------------------------------------------------
__global__ __launch_bounds__(256) void score_kernel(
    const float* __restrict__ q,
    const float* __restrict__ mb,
    const float* __restrict__ imp,
    const float* __restrict__ age)
{
    const int p   = (int)((blockIdx.x * 7u) & 4095u);   // bijection on [0,4096)
    const int r0  = p * 2;
    const int r1  = r0 + 1;
    const int tid = threadIdx.x;
    const float4* m0 = reinterpret_cast<const float4*>(mb) + (size_t)r0 * NV4;
    const float4* m1 = reinterpret_cast<const float4*>(mb) + (size_t)r1 * NV4;
    const float4* qv = reinterpret_cast<const float4*>(q);

    float d0 = 0.f, n0 = 0.f, d1 = 0.f, n1 = 0.f, qn = 0.f;
    #pragma unroll
    for (int u = 0; u < 4; u++) {
        int i = tid + u * 256;
        float4 a0 = __ldcs(&m0[i]);
        float4 a1 = __ldcs(&m1[i]);
        float4 b  = qv[i];
        d0 += a0.x * b.x + a0.y * b.y + a0.z * b.z + a0.w * b.w;
        n0 += a0.x * a0.x + a0.y * a0.y + a0.z * a0.z + a0.w * a0.w;
        d1 += a1.x * b.x + a1.y * b.y + a1.z * b.z + a1.w * b.w;
        n1 += a1.x * a1.x + a1.y * a1.y + a1.z * a1.z + a1.w * a1.w;
        qn += b.x * b.x + b.y * b.y + b.z * b.z + b.w * b.w;
    }

    #pragma unroll
    for (int o = 16; o > 0; o >>= 1) {
        d0 += __shfl_down_sync(0xffffffffu, d0, o);
        n0 += __shfl_down_sync(0xffffffffu, n0, o);
        d1 += __shfl_down_sync(0xffffffffu, d1, o);
        n1 += __shfl_down_sync(0xffffffffu, n1, o);
        qn += __shfl_down_sync(0xffffffffu, qn, o);
    }

    __shared__ float s0[8], s1[8], s2[8], s3[8], s4[8];
    const int w = tid >> 5;
    if ((tid & 31) == 0) { s0[w] = d0; s1[w] = n0; s2[w] = d1; s3[w] = n1; s4[w] = qn; }
    __syncthreads();

    if (tid == 0) {
        float D0 = 0.f, N0 = 0.f, D1 = 0.f, N1 = 0.f, Q = 0.f;
        #pragma unroll
        for (int i = 0; i < 8; i++) {
            D0 += s0[i]; N0 += s1[i]; D1 += s2[i]; N1 += s3[i]; Q += s4[i];
        }
        float qs = sqrtf(Q);
        float sim0 = D0 / fmaxf(qs * sqrtf(N0), 1e-8f);
        float sim1 = D1 / fmaxf(qs * sqrtf(N1), 1e-8f);
        g_weighted[r0] = sim0 * imp[r0] * expf(-0.001f * age[r0]);
        g_weighted[r1] = sim1 * imp[r1] * expf(-0.001f * age[r1]);
    }
}

// ---------------------------------------------------------------------------
// Kernel 2: REGISTER-BASED top-8 + gather. Single block, 256 threads.
// Each thread holds 32 scores in registers; 8 argmax rounds via register scan
// + warp shuffle + smem combine, min-index tie-break with atomicMin (matches
// jax top_k tie order). Register cost isolated in this tiny kernel.
// ---------------------------------------------------------------------------
__global__ __launch_bounds__(256) void topk_gather_kernel(const float* __restrict__ mb)
{
    const int tid = threadIdx.x;

    float v[32];
    #pragma unroll
    for (int j = 0; j < 32; j++)
        v[j] = g_weighted[tid + 256 * j];          // coalesced

    __shared__ float s_wmax[8];
    __shared__ float s_gmax;
    __shared__ int   s_arg;
    __shared__ int   s_idx[TOPK];

    for (int k = 0; k < TOPK; k++) {
        float mx = v[0];
        #pragma unroll
        for (int j = 1; j < 32; j++) mx = fmaxf(mx, v[j]);
        #pragma unroll
        for (int o = 16; o > 0; o >>= 1)
            mx = fmaxf(mx, __shfl_xor_sync(0xffffffffu, mx, o));
        if ((tid & 31) == 0) s_wmax[tid >> 5] = mx;
        if (tid == 0) s_arg = 0x7fffffff;
        __syncthreads();
        if (tid == 0) {
            float g = s_wmax[0];
            #pragma unroll
            for (int j = 1; j < 8; j++) g = fmaxf(g, s_wmax[j]);
            s_gmax = g;
        }
        __syncthreads();
        float g = s_gmax;
        #pragma unroll
        for (int j = 0; j < 32; j++)
            if (v[j] == g) atomicMin(&s_arg, tid + 256 * j);   // min index on ties
        __syncthreads();
        int win = s_arg;
        if (tid == 0) s_idx[k] = win;
        if ((win & 255) == tid) v[win >> 8] = -3.0e38f;        // remove winner
        __syncthreads();
    }

    // gather: retrieved = mean of the 8 selected rows (4 float4 per thread)
    const float4* mbv = reinterpret_cast<const float4*>(mb);
    #pragma unroll
    for (int u = 0; u < 4; u++) {
        int j = tid + u * 256;
        float4 acc = make_float4(0.f, 0.f, 0.f, 0.f);
        #pragma unroll
        for (int t = 0; t < TOPK; t++) {
            float4 x = __ldg(&mbv[(size_t)s_idx[t] * NV4 + j]);
            acc.x += x.x; acc.y += x.y; acc.z += x.z; acc.w += x.w;
        }
        reinterpret_cast<float4*>(g_retrieved)[j] =
            make_float4(acc.x * 0.125f, acc.y * 0.125f, acc.z * 0.125f, acc.w * 0.125f);
    }
}

// ---------------------------------------------------------------------------
// Kernel 3: decode GEMV, 2 rows/block, STRIDE-7 PERMUTED block->row-pair map
// (same transform that gave score +7% HBM bw). W_dec default-cached.
// ---------------------------------------------------------------------------
__global__ __launch_bounds__(256) void gemv_kernel(
    const float* __restrict__ W,
    const float* __restrict__ b,
    float* __restrict__ out)
{
    const int p   = (int)((blockIdx.x * 7u) & 2047u);   // bijection on [0,2048)
    const int r0  = p * 2;
    const int r1  = r0 + 1;
    const int tid = threadIdx.x;
    const float4* w0 = reinterpret_cast<const float4*>(W) + (size_t)r0 * NV4;
    const float4* w1 = reinterpret_cast<const float4*>(W) + (size_t)r1 * NV4;
    const float4* rv = reinterpret_cast<const float4*>(g_retrieved);

    float a0 = 0.f, a1 = 0.f;
    #pragma unroll
    for (int u = 0; u < 4; u++) {
        int i = tid + u * 256;
        float4 x0 = __ldg(&w0[i]);
        float4 x1 = __ldg(&w1[i]);
        float4 v  = rv[i];
        a0 += x0.x * v.x + x0.y * v.y + x0.z * v.z + x0.w * v.w;
        a1 += x1.x * v.x + x1.y * v.y + x1.z * v.z + x1.w * v.w;
    }
    #pragma unroll
    for (int o = 16; o > 0; o >>= 1) {
        a0 += __shfl_down_sync(0xffffffffu, a0, o);
        a1 += __shfl_down_sync(0xffffffffu, a1, o);
    }

    __shared__ float sa[8], sb[8];
    const int w = tid >> 5;
    if ((tid & 31) == 0) { sa[w] = a0; sb[w] = a1; }
    __syncthreads();
    if (tid == 0) {
        float t0 = 0.f, t1 = 0.f;
        #pragma unroll
        for (int i = 0; i < 8; i++) { t0 += sa[i]; t1 += sb[i]; }
        out[r0] = t0 + b[r0];
        out[r1] = t1 + b[r1];
    }
}

// ---------------------------------------------------------------------------
extern "C" void kernel_launch(void* const* d_in, const int* in_sizes, int n_in,
                              void* d_out, int out_size)
{
    const float* q   = (const float*)d_in[0];  // [4096]
    const float* mb  = (const float*)d_in[1];  // [8192, 4096]
    const float* imp = (const float*)d_in[2];  // [8192]
    const float* age = (const float*)d_in[3];  // [8192]
    const float* W   = (const float*)d_in[4];  // [4096, 4096]
    const float* b   = (const float*)d_in[5];  // [4096]
    float* out = (float*)d_out;                // [4096]

    score_kernel<<<CAP / 2, 256>>>(q, mb, imp, age);
    topk_gather_kernel<<<1, 256>>>(mb);
    gemv_kernel<<<DIM / 2, 256>>>(W, b, out);
}